// round 9
// baseline (speedup 1.0000x reference)
#include <cuda_runtime.h>

#define NPOINTS 131072
#define INF 512
#define NC 64
#define ROWSTRIDE 513   // 512 features + 1 case id per row of x
#define RBLOCKS 222     // point tiles: grid (2 x 222) = 444 = 148 SMs x 3 CTAs
#define FCHUNK 256      // features per reduce block

// -------- device scratch (static: no allocations allowed) --------
__device__ float g_part[RBLOCKS][NC][INF];     // per-tile partial sums (~29 MB)
__device__ float g_pcnt[RBLOCKS][NC];          // per-tile case counts
__device__ int   g_cid[NPOINTS];               // compact case ids (for scatter)
__device__ __align__(16) float g_mean[NC * INF];     // per-case feature means
__device__ __align__(16) float g_hfinal[NC * INF];   // final MLP output table
__device__ float g_Wt[3][INF * INF];           // scaled transposed weights (k-major)

// ============================================================================
// Kernel 1 (x3 launches): fused weight prep for one matrix. Load 32 rows to
// smem, weight-norm scale g/||row|| (or 1.0), write scaled TRANSPOSED strip.
// ============================================================================
__global__ void prep_kernel(const float* __restrict__ src, const float* __restrict__ g,
                            int m, int has_g) {
    extern __shared__ float sm[];              // 32*513 row cache + 32 scales
    float* srow   = sm;
    float* sscale = sm + 32 * 513;
    const int ob = blockIdx.x * 32;
    const int t = threadIdx.x;

    for (int idx = t; idx < 32 * 512; idx += 256) {
        int r = idx >> 9, k = idx & 511;
        srow[r * 513 + k] = src[(size_t)(ob + r) * INF + k];
    }
    __syncthreads();

    const int w = t >> 5, lane = t & 31;
#pragma unroll
    for (int rr = 0; rr < 4; rr++) {
        int r = w * 4 + rr;
        float ss = 0.f;
        for (int k = lane; k < INF; k += 32) {
            float v = srow[r * 513 + k];
            ss = fmaf(v, v, ss);
        }
        for (int off = 16; off; off >>= 1) ss += __shfl_down_sync(0xffffffffu, ss, off);
        if (lane == 0) sscale[r] = has_g ? (g[ob + r] * rsqrtf(ss)) : 1.f;
    }
    __syncthreads();

    const float scl = sscale[lane];
#pragma unroll 8
    for (int j = 0; j < 64; j++) {
        int k = w + 8 * j;
        g_Wt[m][(size_t)k * INF + ob + lane] = srow[lane * 513 + k] * scl;
    }
}

// ============================================================================
// Kernel 2: per-case partial sums, software-pipelined. All 256 threads handle
// the SAME point each step -> thread t exclusively owns feature lane t of the
// smem accumulator. Double-buffered 8-point batches: batch n+1's 16 LDGs issue
// before batch n's serialized smem RMW chain (LDG is independent of STS).
// Counts via 8 parallel smem atomics; cids via 8 parallel STGs (chunk 1).
// ============================================================================
__device__ __forceinline__ void load8(const float* __restrict__ x, int p, int cbase,
                                      int t, float* v, int* c) {
#pragma unroll
    for (int i = 0; i < 8; i++) {
        const float* row = x + (size_t)(p + i) * ROWSTRIDE;
        v[i] = __ldcs(row + cbase + t);
        c[i] = __float2int_rn(__ldcs(row + INF));   // cid: exact small int
    }
}

__global__ __launch_bounds__(256, 3)
void reduce_kernel(const float* __restrict__ x) {
    extern __shared__ float sacc[];            // NC*FCHUNK accum + NC counts
    float* cnt = sacc + NC * FCHUNK;
    const int chunk = blockIdx.x;              // 0..1 -> feature half
    const int pt    = blockIdx.y;              // 0..RBLOCKS-1 -> point tile
    const int t     = threadIdx.x;             // 0..255
    const int cbase = chunk * FCHUNK;

    for (int i = t; i < NC * FCHUNK; i += 256) sacc[i] = 0.f;
    if (chunk == 0 && t < NC) cnt[t] = 0.f;
    __syncthreads();

    const int per = (NPOINTS + RBLOCKS - 1) / RBLOCKS;   // 591
    int p0 = pt * per;
    int p1 = p0 + per; if (p1 > NPOINTS) p1 = NPOINTS;

    const int nfull = (p1 - p0) >> 3;          // full 8-point batches
    float v[2][8]; int c[2][8];
    if (nfull > 0) load8(x, p0, cbase, t, v[0], c[0]);

    for (int b = 0; b < nfull; b++) {
        const int cur = b & 1;
        if (b + 1 < nfull) load8(x, p0 + (b + 1) * 8, cbase, t, v[cur ^ 1], c[cur ^ 1]);
        const int pbase = p0 + b * 8;
#pragma unroll
        for (int i = 0; i < 8; i++) sacc[c[cur][i] * FCHUNK + t] += v[cur][i];
        if (t < 8) {
            // thread t takes point pbase+t's cid (all threads hold all 8 cids)
            int myc = c[cur][0];
#pragma unroll
            for (int i = 1; i < 8; i++) myc = (t == i) ? c[cur][i] : myc;
            if (chunk == 0) atomicAdd(&cnt[myc], 1.f);
            else            g_cid[pbase + t] = myc;
        }
    }
    // tail (<8 points)
    for (int p = p0 + nfull * 8; p < p1; p++) {
        const float* row = x + (size_t)p * ROWSTRIDE;
        int cc = __float2int_rn(__ldcs(row + INF));
        sacc[cc * FCHUNK + t] += __ldcs(row + cbase + t);
        if (chunk == 0 && t == 0) cnt[cc] += 1.f;
        if (chunk == 1 && t == 0) g_cid[p] = cc;
    }
    __syncthreads();

    for (int i = t; i < NC * FCHUNK; i += 256) {
        int cc = i >> 8;         // i / FCHUNK
        int f  = i & (FCHUNK - 1);
        g_part[pt][cc][cbase + f] = sacc[i];
    }
    if (chunk == 0 && t < NC) g_pcnt[pt][t] = cnt[t];
}

// ============================================================================
// Kernel 3: mean. grid (64 cases x 2 f-halves) x 1024 threads. Threads split
// the 222 partial tiles 4 ways (f_local = t&255, pg = t>>8) -> MLP ~16/feature.
// ============================================================================
__global__ __launch_bounds__(1024)
void mean_kernel() {
    __shared__ float sred[4][256];
    __shared__ float scnt;
    const int c    = blockIdx.x;
    const int half = blockIdx.y;
    const int t    = threadIdx.x;
    const int fl   = t & 255;
    const int pg   = t >> 8;                   // 0..3
    const int f    = half * 256 + fl;

    int q0 = pg * 56;
    int q1 = q0 + 56; if (q1 > RBLOCKS) q1 = RBLOCKS;
    float a0 = 0.f, a1 = 0.f, a2 = 0.f, a3 = 0.f;
    int q = q0;
    for (; q + 4 <= q1; q += 4) {
        a0 += g_part[q + 0][c][f];
        a1 += g_part[q + 1][c][f];
        a2 += g_part[q + 2][c][f];
        a3 += g_part[q + 3][c][f];
    }
    for (; q < q1; q++) a0 += g_part[q][c][f];
    sred[pg][fl] = (a0 + a1) + (a2 + a3);

    if (t < 32) {
        float cn = 0.f;
        for (int qq = t; qq < RBLOCKS; qq += 32) cn += g_pcnt[qq][c];
        for (int off = 16; off; off >>= 1) cn += __shfl_down_sync(0xffffffffu, cn, off);
        if (t == 0) scnt = fmaxf(cn, 1.f);
    }
    __syncthreads();

    if (pg == 0)
        g_mean[c * INF + f] = (sred[0][fl] + sred[1][fl] + sred[2][fl] + sred[3][fl]) / scnt;
}

// ============================================================================
// Kernel 4: 3-layer MLP on the 64x512 mean table. grid 16 blocks x 512 thr,
// 4 cases/block, 2-way k-split accumulators -> 16 outstanding L2-hot weight
// loads per thread, weight L2 traffic 48 MB total.
// ============================================================================
__global__ __launch_bounds__(512)
void mlp_kernel(const float* __restrict__ b0, const float* __restrict__ b1,
                const float* __restrict__ bf) {
    __shared__ float hs[4][INF];
    const int t  = threadIdx.x;
    const int c0 = blockIdx.x * 4;

#pragma unroll
    for (int ci = 0; ci < 4; ci++) hs[ci][t] = g_mean[(size_t)(c0 + ci) * INF + t];
    __syncthreads();

    for (int L = 0; L < 3; L++) {
        const float* Wt = g_Wt[L];
        float aL[4] = {0.f, 0.f, 0.f, 0.f};
        float aH[4] = {0.f, 0.f, 0.f, 0.f};
#pragma unroll 8
        for (int k = 0; k < 256; k++) {
            float w0 = Wt[(size_t)k * INF + t];
            float w1 = Wt[(size_t)(k + 256) * INF + t];
#pragma unroll
            for (int ci = 0; ci < 4; ci++) {
                aL[ci] = fmaf(hs[ci][k],       w0, aL[ci]);
                aH[ci] = fmaf(hs[ci][k + 256], w1, aH[ci]);
            }
        }
        const float* bb = (L == 0) ? b0 : ((L == 1) ? b1 : bf);
        const float bias = bb[t];
        float vv[4];
#pragma unroll
        for (int ci = 0; ci < 4; ci++) {
            float v = aL[ci] + aH[ci] + bias;
            if (L < 2) v = v * (1.f / (1.f + __expf(-v)));
            vv[ci] = v;
        }
        __syncthreads();
        if (L < 2) {
#pragma unroll
            for (int ci = 0; ci < 4; ci++) hs[ci][t] = vv[ci];
            __syncthreads();
        } else {
#pragma unroll
            for (int ci = 0; ci < 4; ci++)
                g_hfinal[(size_t)(c0 + ci) * INF + t] = vv[ci];
        }
    }
}

// ============================================================================
// Kernel 5: scatter out[p][:] = h_final[cid[p]][:].  64 points/block; cids
// staged in smem; float4 streaming stores (out is never re-read).
// ============================================================================
__global__ void scatter_kernel(float* __restrict__ out) {
    __shared__ int sc[64];
    const int t = threadIdx.x;                 // 0..255
    const int p0 = blockIdx.x * 64;
    if (t < 64) sc[t] = g_cid[p0 + t];
    __syncthreads();
    const int pl = t >> 7;                     // 0 or 1
    const int f4 = t & 127;                    // float4 index within 512-float row
    const float4* h4 = (const float4*)g_hfinal;
    float4* o4 = (float4*)out;
#pragma unroll 8
    for (int i = pl; i < 64; i += 2) {
        int c = sc[i];
        float4 v = h4[c * 128 + f4];
        __stcs(&o4[(size_t)(p0 + i) * 128 + f4], v);
    }
}

// ============================================================================
extern "C" void kernel_launch(void* const* d_in, const int* in_sizes, int n_in,
                              void* d_out, int out_size) {
    const float* x  = (const float*)d_in[0];
    const float* V0 = (const float*)d_in[1];
    const float* g0 = (const float*)d_in[2];
    const float* b0 = (const float*)d_in[3];
    const float* V1 = (const float*)d_in[4];
    const float* g1 = (const float*)d_in[5];
    const float* b1 = (const float*)d_in[6];
    const float* Wf = (const float*)d_in[7];
    const float* bf = (const float*)d_in[8];
    float* out = (float*)d_out;

    const int red_smem  = (NC * FCHUNK + NC) * (int)sizeof(float);  // 65792 B
    const int prep_smem = (32 * 513 + 32) * (int)sizeof(float);     // 65792 B
    cudaFuncSetAttribute(reduce_kernel,
                         cudaFuncAttributeMaxDynamicSharedMemorySize, red_smem);
    cudaFuncSetAttribute(prep_kernel,
                         cudaFuncAttributeMaxDynamicSharedMemorySize, prep_smem);

    // prep split into 3 launches so reduce lands in ncu capture slot #4.
    prep_kernel<<<16, 256, prep_smem>>>(V0, g0, 0, 1);              // 1
    prep_kernel<<<16, 256, prep_smem>>>(V1, g1, 1, 1);              // 2
    prep_kernel<<<16, 256, prep_smem>>>(Wf, bf, 2, 0);              // 3
    reduce_kernel<<<dim3(2, RBLOCKS), 256, red_smem>>>(x);          // 4  <-- profile me
    mean_kernel<<<dim3(NC, 2), 1024>>>();                           // 5
    mlp_kernel<<<16, 512>>>(b0, b1, bf);                            // 6
    scatter_kernel<<<2048, 256>>>(out);                             // 7
}

// round 12
// speedup vs baseline: 1.3122x; 1.3122x over previous
#include <cuda_runtime.h>

#define NPOINTS 131072
#define INF 512
#define NC 64
#define ROWSTRIDE 513   // 512 features + 1 case id per row of x
#define NR 8            // point ranges for the gather-reduce
#define RANGE 16384     // NPOINTS / NR
#define SEG 4096        // compaction segment (bounds smem match list safely)

// -------- device scratch (static: no allocations allowed) --------
__device__ int   g_cid[NPOINTS];               // compact case ids
__device__ float g_part2[NR][NC][INF];         // per-range per-case sums (1 MB)
__device__ float g_pcnt2[NR][NC];              // per-range case counts
__device__ __align__(16) float g_mean[NC * INF];     // per-case feature means
__device__ __align__(16) float g_hfinal[NC * INF];   // final MLP output table
__device__ float g_Wt[3][INF * INF];           // scaled transposed weights (k-major)

// ============================================================================
// Kernel 1: extract compact cids. 1 sector per row; feeds gather + scatter.
// ============================================================================
__global__ void cid_kernel(const float* __restrict__ x) {
    const int p = blockIdx.x * 256 + threadIdx.x;
    g_cid[p] = __float2int_rn(__ldcs(x + (size_t)p * ROWSTRIDE + INF));
}

// ============================================================================
// Kernel 2 (x3 launches): weight prep for one matrix. Load 32 rows to smem,
// weight-norm scale g/||row|| (or 1.0), write scaled TRANSPOSED strip.
// ============================================================================
__global__ void prep_kernel(const float* __restrict__ src, const float* __restrict__ g,
                            int m, int has_g) {
    extern __shared__ float sm[];              // 32*513 row cache + 32 scales
    float* srow   = sm;
    float* sscale = sm + 32 * 513;
    const int ob = blockIdx.x * 32;
    const int t = threadIdx.x;

    for (int idx = t; idx < 32 * 512; idx += 256) {
        int r = idx >> 9, k = idx & 511;
        srow[r * 513 + k] = src[(size_t)(ob + r) * INF + k];
    }
    __syncthreads();

    const int w = t >> 5, lane = t & 31;
#pragma unroll
    for (int rr = 0; rr < 4; rr++) {
        int r = w * 4 + rr;
        float ss = 0.f;
        for (int k = lane; k < INF; k += 32) {
            float v = srow[r * 513 + k];
            ss = fmaf(v, v, ss);
        }
        for (int off = 16; off; off >>= 1) ss += __shfl_down_sync(0xffffffffu, ss, off);
        if (lane == 0) sscale[r] = has_g ? (g[ob + r] * rsqrtf(ss)) : 1.f;
    }
    __syncthreads();

    const float scl = sscale[lane];
#pragma unroll 8
    for (int j = 0; j < 64; j++) {
        int k = w + 8 * j;
        g_Wt[m][(size_t)k * INF + ob + lane] = srow[lane * 513 + k] * scl;
    }
}

// ============================================================================
// Kernel 3: gather-reduce. Block (c, r) compacts indices of points in range r
// with cid==c into smem (order-independent atomic append), then streams those
// rows with PURE REGISTER accumulation: no smem RMW, no aliasing hazard, no
// divergence (all 512 threads agree on every branch). Thread t = feature t.
// 8 predicated LDGs per batch -> 8 outstanding DRAM loads per thread.
// ============================================================================
__global__ __launch_bounds__(512, 2)
void gather_kernel(const float* __restrict__ x) {
    __shared__ int smatch[SEG];
    __shared__ int scount;
    const int c = blockIdx.x;                  // case 0..63
    const int r = blockIdx.y;                  // range 0..7
    const int t = threadIdx.x;                 // feature 0..511
    const int base = r * RANGE;

    float acc0 = 0.f, acc1 = 0.f;
    int total = 0;

    for (int seg = 0; seg < RANGE / SEG; seg++) {
        if (t == 0) scount = 0;
        __syncthreads();
        const int sbase = base + seg * SEG;
        for (int i = t; i < SEG; i += 512) {
            if (g_cid[sbase + i] == c)
                smatch[atomicAdd(&scount, 1)] = sbase + i;
        }
        __syncthreads();
        const int n = scount;
        total += n;
        for (int j = 0; j < n; j += 8) {
            float v[8];
#pragma unroll
            for (int i = 0; i < 8; i++) {
                v[i] = 0.f;
                if (j + i < n) {
                    int p = smatch[j + i];
                    v[i] = __ldcs(x + (size_t)p * ROWSTRIDE + t);
                }
            }
            acc0 += ((v[0] + v[1]) + (v[2] + v[3]));
            acc1 += ((v[4] + v[5]) + (v[6] + v[7]));
        }
        __syncthreads();                       // protect smatch/scount reuse
    }
    g_part2[r][c][t] = acc0 + acc1;
    if (t == 0) g_pcnt2[r][c] = (float)total;
}

// ============================================================================
// Kernel 4: merge 8 range-partials into per-case means. grid 64 x 512.
// ============================================================================
__global__ void mean8_kernel() {
    const int c = blockIdx.x;
    const int t = threadIdx.x;
    float s = 0.f, cn = 0.f;
#pragma unroll
    for (int r = 0; r < NR; r++) {
        s  += g_part2[r][c][t];
        cn += g_pcnt2[r][c];
    }
    g_mean[c * INF + t] = s / fmaxf(cn, 1.f);
}

// ============================================================================
// Kernel 5: 3-layer MLP on the 64x512 mean table. grid 16 blocks x 512 thr,
// 4 cases/block, 2-way k-split accumulators (16 outstanding weight loads).
// ============================================================================
__global__ __launch_bounds__(512)
void mlp_kernel(const float* __restrict__ b0, const float* __restrict__ b1,
                const float* __restrict__ bf) {
    __shared__ float hs[4][INF];
    const int t  = threadIdx.x;
    const int c0 = blockIdx.x * 4;

#pragma unroll
    for (int ci = 0; ci < 4; ci++) hs[ci][t] = g_mean[(size_t)(c0 + ci) * INF + t];
    __syncthreads();

    for (int L = 0; L < 3; L++) {
        const float* Wt = g_Wt[L];
        float aL[4] = {0.f, 0.f, 0.f, 0.f};
        float aH[4] = {0.f, 0.f, 0.f, 0.f};
#pragma unroll 8
        for (int k = 0; k < 256; k++) {
            float w0 = Wt[(size_t)k * INF + t];
            float w1 = Wt[(size_t)(k + 256) * INF + t];
#pragma unroll
            for (int ci = 0; ci < 4; ci++) {
                aL[ci] = fmaf(hs[ci][k],       w0, aL[ci]);
                aH[ci] = fmaf(hs[ci][k + 256], w1, aH[ci]);
            }
        }
        const float* bb = (L == 0) ? b0 : ((L == 1) ? b1 : bf);
        const float bias = bb[t];
        float vv[4];
#pragma unroll
        for (int ci = 0; ci < 4; ci++) {
            float v = aL[ci] + aH[ci] + bias;
            if (L < 2) v = v * (1.f / (1.f + __expf(-v)));
            vv[ci] = v;
        }
        __syncthreads();
        if (L < 2) {
#pragma unroll
            for (int ci = 0; ci < 4; ci++) hs[ci][t] = vv[ci];
            __syncthreads();
        } else {
#pragma unroll
            for (int ci = 0; ci < 4; ci++)
                g_hfinal[(size_t)(c0 + ci) * INF + t] = vv[ci];
        }
    }
}

// ============================================================================
// Kernel 6: scatter out[p][:] = h_final[cid[p]][:].  64 points/block; cids
// staged in smem; float4 streaming stores (near roofline at 42.7us in R8).
// ============================================================================
__global__ void scatter_kernel(float* __restrict__ out) {
    __shared__ int sc[64];
    const int t = threadIdx.x;                 // 0..255
    const int p0 = blockIdx.x * 64;
    if (t < 64) sc[t] = g_cid[p0 + t];
    __syncthreads();
    const int pl = t >> 7;                     // 0 or 1
    const int f4 = t & 127;                    // float4 index within 512-float row
    const float4* h4 = (const float4*)g_hfinal;
    float4* o4 = (float4*)out;
#pragma unroll 8
    for (int i = pl; i < 64; i += 2) {
        int c = sc[i];
        float4 v = h4[c * 128 + f4];
        __stcs(&o4[(size_t)(p0 + i) * 128 + f4], v);
    }
}

// ============================================================================
extern "C" void kernel_launch(void* const* d_in, const int* in_sizes, int n_in,
                              void* d_out, int out_size) {
    const float* x  = (const float*)d_in[0];
    const float* V0 = (const float*)d_in[1];
    const float* g0 = (const float*)d_in[2];
    const float* b0 = (const float*)d_in[3];
    const float* V1 = (const float*)d_in[4];
    const float* g1 = (const float*)d_in[5];
    const float* b1 = (const float*)d_in[6];
    const float* Wf = (const float*)d_in[7];
    const float* bf = (const float*)d_in[8];
    float* out = (float*)d_out;

    const int prep_smem = (32 * 513 + 32) * (int)sizeof(float);     // 65792 B
    cudaFuncSetAttribute(prep_kernel,
                         cudaFuncAttributeMaxDynamicSharedMemorySize, prep_smem);

    // Ordered so gather_kernel lands in ncu capture slot #4.
    cid_kernel<<<NPOINTS / 256, 256>>>(x);                          // 1
    prep_kernel<<<16, 256, prep_smem>>>(V0, g0, 0, 1);              // 2
    prep_kernel<<<16, 256, prep_smem>>>(V1, g1, 1, 1);              // 3
    gather_kernel<<<dim3(NC, NR), 512>>>(x);                        // 4  <-- profile me
    prep_kernel<<<16, 256, prep_smem>>>(Wf, bf, 2, 0);              // 5
    mean8_kernel<<<NC, 512>>>();                                    // 6
    mlp_kernel<<<16, 512>>>(b0, b1, bf);                            // 7
    scatter_kernel<<<2048, 256>>>(out);                             // 8
}

// round 13
// speedup vs baseline: 1.5751x; 1.2003x over previous
#include <cuda_runtime.h>

#define NPOINTS 131072
#define INF 512
#define NC 64
#define ROWSTRIDE 513   // 512 features + 1 case id per row of x
#define NR 8            // point ranges for the gather-reduce
#define RANGE 16384     // NPOINTS / NR
#define SEG 8192        // compaction segment (32 KB smem match list)

// -------- device scratch (static: no allocations allowed) --------
__device__ int   g_cid[NPOINTS];               // compact case ids
__device__ float g_part2[NR][NC][INF];         // per-range per-case sums (1 MB)
__device__ float g_pcnt2[NR][NC];              // per-range case counts
__device__ __align__(16) float g_mean[NC * INF];     // per-case feature means
__device__ __align__(16) float g_hfinal[NC * INF];   // final MLP output table
__device__ float g_scale[2 * INF];             // weight-norm scales, layers 0,1
__device__ float g_Wt[3][INF * INF];           // scaled transposed weights (k-major)

// ============================================================================
// Kernel 1: weight-norm row scales g[o]/||V[o]||. 1024 warps, one per row.
// ============================================================================
__global__ void norm_kernel(const float* __restrict__ V0, const float* __restrict__ g0,
                            const float* __restrict__ V1, const float* __restrict__ g1) {
    const int w    = blockIdx.x * (blockDim.x >> 5) + (threadIdx.x >> 5);
    const int lane = threadIdx.x & 31;
    const int layer = w >> 9;
    const int o     = w & 511;
    const float* V = layer ? V1 : V0;
    const float* g = layer ? g1 : g0;
    float ss = 0.f;
    for (int k = lane; k < INF; k += 32) {
        float v = V[(size_t)o * INF + k];
        ss = fmaf(v, v, ss);
    }
    for (int off = 16; off; off >>= 1) ss += __shfl_down_sync(0xffffffffu, ss, off);
    if (lane == 0) g_scale[layer * INF + o] = g[o] * rsqrtf(ss);
}

// ============================================================================
// Kernel 2: wide scaled transpose (R2-measured 5.2us at this exact shape).
// Wt[k][o] = src[o][k] * scale[o] (scale 1.0 for Wf). 32x32 smem tiles,
// grid (16, 16, 3) = 768 blocks.
// ============================================================================
__global__ void prep_wide(const float* __restrict__ V0, const float* __restrict__ V1,
                          const float* __restrict__ Wf) {
    __shared__ float tile[32][33];
    const int m = blockIdx.z;                        // 0: V0, 1: V1, 2: Wf
    const float* src = (m == 0) ? V0 : ((m == 1) ? V1 : Wf);
    const int ob = blockIdx.y * 32;
    const int kb = blockIdx.x * 32;
    const int tx = threadIdx.x, ty = threadIdx.y;
#pragma unroll
    for (int j = 0; j < 32; j += 8) {
        int o = ob + ty + j;
        float sc = (m < 2) ? g_scale[m * INF + o] : 1.f;
        tile[ty + j][tx] = src[(size_t)o * INF + kb + tx] * sc;
    }
    __syncthreads();
#pragma unroll
    for (int j = 0; j < 32; j += 8) {
        g_Wt[m][(size_t)(kb + ty + j) * INF + ob + tx] = tile[tx][ty + j];
    }
}

// ============================================================================
// Kernel 3: extract compact cids. 1 sector per row; feeds gather + scatter.
// ============================================================================
__global__ void cid_kernel(const float* __restrict__ x) {
    const int p = blockIdx.x * 256 + threadIdx.x;
    g_cid[p] = __float2int_rn(__ldcs(x + (size_t)p * ROWSTRIDE + INF));
}

// ============================================================================
// Kernel 4: gather-reduce (R12: 58.1us @ 59.5% DRAM). Block (c, r) compacts
// indices of points with cid==c into smem, then streams those rows with pure
// register accumulation (no smem RMW, no divergence). SEG doubled to 8192 to
// halve the serial scan/barrier phases between load bursts.
// ============================================================================
__global__ __launch_bounds__(512, 2)
void gather_kernel(const float* __restrict__ x) {
    __shared__ int smatch[SEG];
    __shared__ int scount;
    const int c = blockIdx.x;                  // case 0..63
    const int r = blockIdx.y;                  // range 0..7
    const int t = threadIdx.x;                 // feature 0..511
    const int base = r * RANGE;

    float acc0 = 0.f, acc1 = 0.f;
    int total = 0;

    for (int seg = 0; seg < RANGE / SEG; seg++) {
        if (t == 0) scount = 0;
        __syncthreads();
        const int sbase = base + seg * SEG;
        for (int i = t; i < SEG; i += 512) {
            if (g_cid[sbase + i] == c)
                smatch[atomicAdd(&scount, 1)] = sbase + i;
        }
        __syncthreads();
        const int n = scount;
        total += n;
        for (int j = 0; j < n; j += 8) {
            float v[8];
#pragma unroll
            for (int i = 0; i < 8; i++) {
                v[i] = 0.f;
                if (j + i < n) {
                    int p = smatch[j + i];
                    v[i] = __ldcs(x + (size_t)p * ROWSTRIDE + t);
                }
            }
            acc0 += ((v[0] + v[1]) + (v[2] + v[3]));
            acc1 += ((v[4] + v[5]) + (v[6] + v[7]));
        }
        __syncthreads();                       // protect smatch/scount reuse
    }
    g_part2[r][c][t] = acc0 + acc1;
    if (t == 0) g_pcnt2[r][c] = (float)total;
}

// ============================================================================
// Kernel 5: merge 8 range-partials into per-case means. grid 64 x 512.
// ============================================================================
__global__ void mean8_kernel() {
    const int c = blockIdx.x;
    const int t = threadIdx.x;
    float s = 0.f, cn = 0.f;
#pragma unroll
    for (int r = 0; r < NR; r++) {
        s  += g_part2[r][c][t];
        cn += g_pcnt2[r][c];
    }
    g_mean[c * INF + t] = s / fmaxf(cn, 1.f);
}

// ============================================================================
// Kernel 6: 3-layer MLP, one case per block (64 blocks x 512 threads).
// 8-way k-split accumulators: all weight loads independent, L2-hot.
// ============================================================================
__global__ __launch_bounds__(512)
void mlp_kernel(const float* __restrict__ b0, const float* __restrict__ b1,
                const float* __restrict__ bf) {
    __shared__ float hs[INF];
    const int t = threadIdx.x;
    const int c = blockIdx.x;

    hs[t] = g_mean[(size_t)c * INF + t];
    __syncthreads();

    for (int L = 0; L < 3; L++) {
        const float* Wt = g_Wt[L];
        float a[8] = {0.f, 0.f, 0.f, 0.f, 0.f, 0.f, 0.f, 0.f};
#pragma unroll 8
        for (int k = 0; k < 64; k++) {
#pragma unroll
            for (int s = 0; s < 8; s++) {
                int kk = s * 64 + k;
                a[s] = fmaf(hs[kk], Wt[(size_t)kk * INF + t], a[s]);
            }
        }
        const float* bb = (L == 0) ? b0 : ((L == 1) ? b1 : bf);
        float v = ((a[0] + a[1]) + (a[2] + a[3])) + ((a[4] + a[5]) + (a[6] + a[7])) + bb[t];
        if (L < 2) {
            v = v * (1.f / (1.f + __expf(-v)));
            __syncthreads();
            hs[t] = v;
            __syncthreads();
        } else {
            g_hfinal[(size_t)c * INF + t] = v;
        }
    }
}

// ============================================================================
// Kernel 7: scatter out[p][:] = h_final[cid[p]][:] (R8: 42.7us @ 62% DRAM).
// ============================================================================
__global__ void scatter_kernel(float* __restrict__ out) {
    __shared__ int sc[64];
    const int t = threadIdx.x;                 // 0..255
    const int p0 = blockIdx.x * 64;
    if (t < 64) sc[t] = g_cid[p0 + t];
    __syncthreads();
    const int pl = t >> 7;                     // 0 or 1
    const int f4 = t & 127;                    // float4 index within 512-float row
    const float4* h4 = (const float4*)g_hfinal;
    float4* o4 = (float4*)out;
#pragma unroll 8
    for (int i = pl; i < 64; i += 2) {
        int c = sc[i];
        float4 v = h4[c * 128 + f4];
        __stcs(&o4[(size_t)(p0 + i) * 128 + f4], v);
    }
}

// ============================================================================
extern "C" void kernel_launch(void* const* d_in, const int* in_sizes, int n_in,
                              void* d_out, int out_size) {
    const float* x  = (const float*)d_in[0];
    const float* V0 = (const float*)d_in[1];
    const float* g0 = (const float*)d_in[2];
    const float* b0 = (const float*)d_in[3];
    const float* V1 = (const float*)d_in[4];
    const float* g1 = (const float*)d_in[5];
    const float* b1 = (const float*)d_in[6];
    const float* Wf = (const float*)d_in[7];
    const float* bf = (const float*)d_in[8];
    float* out = (float*)d_out;

    // Ordered so gather_kernel lands in ncu capture slot #4.
    norm_kernel<<<128, 256>>>(V0, g0, V1, g1);                      // 1
    prep_wide<<<dim3(16, 16, 3), dim3(32, 8)>>>(V0, V1, Wf);        // 2
    cid_kernel<<<NPOINTS / 256, 256>>>(x);                          // 3
    gather_kernel<<<dim3(NC, NR), 512>>>(x);                        // 4  <-- profile me
    mean8_kernel<<<NC, 512>>>();                                    // 5
    mlp_kernel<<<NC, 512>>>(b0, b1, bf);                            // 6
    scatter_kernel<<<2048, 256>>>(out);                             // 7
}

// round 14
// speedup vs baseline: 1.6651x; 1.0571x over previous
#include <cuda_runtime.h>

#define NPOINTS 131072
#define INF 512
#define NC 64
#define ROWSTRIDE 513   // 512 features + 1 case id per row of x
#define NR 8            // point ranges for the gather-reduce
#define RANGE 16384     // NPOINTS / NR
#define SEG 4096        // compaction segment (R12-measured best; 8192 regressed)

// -------- device scratch (static: no allocations allowed) --------
__device__ int   g_cid[NPOINTS];               // compact case ids
__device__ float g_part2[NR][NC][INF];         // per-range per-case sums (1 MB)
__device__ float g_pcnt2[NR][NC];              // per-range case counts
__device__ __align__(16) float g_hfinal[NC * INF];   // final MLP output table
__device__ float g_scale[2 * INF];             // weight-norm scales, layers 0,1
__device__ float g_Wt[3][INF * INF];           // scaled transposed weights (k-major)

// ============================================================================
// Kernel 1: fused cid-extract + weight-norm scales (disjoint block ranges).
// Blocks [0,512): g_cid[p] from x. Blocks [512,640): one warp per weight row,
// scale = g[o] * rsqrt(||V[o]||^2).
// ============================================================================
__global__ void combo_kernel(const float* __restrict__ x,
                             const float* __restrict__ V0, const float* __restrict__ g0,
                             const float* __restrict__ V1, const float* __restrict__ g1) {
    const int b = blockIdx.x;
    const int t = threadIdx.x;
    if (b < 512) {
        const int p = b * 256 + t;
        g_cid[p] = __float2int_rn(__ldcs(x + (size_t)p * ROWSTRIDE + INF));
    } else {
        const int w    = (b - 512) * 8 + (t >> 5);   // 0..1023
        const int lane = t & 31;
        const int layer = w >> 9;
        const int o     = w & 511;
        const float* V = layer ? V1 : V0;
        const float* g = layer ? g1 : g0;
        float ss = 0.f;
        for (int k = lane; k < INF; k += 32) {
            float v = V[(size_t)o * INF + k];
            ss = fmaf(v, v, ss);
        }
        for (int off = 16; off; off >>= 1) ss += __shfl_down_sync(0xffffffffu, ss, off);
        if (lane == 0) g_scale[layer * INF + o] = g[o] * rsqrtf(ss);
    }
}

// ============================================================================
// Kernel 2: wide scaled transpose (R2-measured ~5.2us at this shape).
// Wt[k][o] = src[o][k] * scale[o] (scale 1.0 for Wf). grid (16,16,3).
// ============================================================================
__global__ void prep_wide(const float* __restrict__ V0, const float* __restrict__ V1,
                          const float* __restrict__ Wf) {
    __shared__ float tile[32][33];
    const int m = blockIdx.z;                        // 0: V0, 1: V1, 2: Wf
    const float* src = (m == 0) ? V0 : ((m == 1) ? V1 : Wf);
    const int ob = blockIdx.y * 32;
    const int kb = blockIdx.x * 32;
    const int tx = threadIdx.x, ty = threadIdx.y;
#pragma unroll
    for (int j = 0; j < 32; j += 8) {
        int o = ob + ty + j;
        float sc = (m < 2) ? g_scale[m * INF + o] : 1.f;
        tile[ty + j][tx] = src[(size_t)o * INF + kb + tx] * sc;
    }
    __syncthreads();
#pragma unroll
    for (int j = 0; j < 32; j += 8) {
        g_Wt[m][(size_t)(kb + ty + j) * INF + ob + tx] = tile[tx][ty + j];
    }
}

// ============================================================================
// Kernel 3: gather-reduce (R12: 58.1us @ 59.5% DRAM with SEG=4096). Block
// (c, r) compacts indices of points with cid==c into smem, then streams those
// rows with pure register accumulation (no smem RMW, no divergence).
// ============================================================================
__global__ __launch_bounds__(512, 2)
void gather_kernel(const float* __restrict__ x) {
    __shared__ int smatch[SEG];
    __shared__ int scount;
    const int c = blockIdx.x;                  // case 0..63
    const int r = blockIdx.y;                  // range 0..7
    const int t = threadIdx.x;                 // feature 0..511
    const int base = r * RANGE;

    float acc0 = 0.f, acc1 = 0.f;
    int total = 0;

    for (int seg = 0; seg < RANGE / SEG; seg++) {
        if (t == 0) scount = 0;
        __syncthreads();
        const int sbase = base + seg * SEG;
        for (int i = t; i < SEG; i += 512) {
            if (g_cid[sbase + i] == c)
                smatch[atomicAdd(&scount, 1)] = sbase + i;
        }
        __syncthreads();
        const int n = scount;
        total += n;
        for (int j = 0; j < n; j += 8) {
            float v[8];
#pragma unroll
            for (int i = 0; i < 8; i++) {
                v[i] = 0.f;
                if (j + i < n) {
                    int p = smatch[j + i];
                    v[i] = __ldcs(x + (size_t)p * ROWSTRIDE + t);
                }
            }
            acc0 += ((v[0] + v[1]) + (v[2] + v[3]));
            acc1 += ((v[4] + v[5]) + (v[6] + v[7]));
        }
        __syncthreads();                       // protect smatch/scount reuse
    }
    g_part2[r][c][t] = acc0 + acc1;
    if (t == 0) g_pcnt2[r][c] = (float)total;
}

// ============================================================================
// Kernel 4: fused mean-merge + 3-layer MLP, one case per block (64 x 512).
// Merge 8 range-partials in registers -> hs, then 3 matvec layers with 8-way
// k-split accumulators (all weight loads independent, L2-hot).
// ============================================================================
__global__ __launch_bounds__(512)
void mlp_kernel(const float* __restrict__ b0, const float* __restrict__ b1,
                const float* __restrict__ bf) {
    __shared__ float hs[INF];
    const int t = threadIdx.x;
    const int c = blockIdx.x;

    {
        float s = 0.f, cn = 0.f;
#pragma unroll
        for (int r = 0; r < NR; r++) {
            s  += g_part2[r][c][t];
            cn += g_pcnt2[r][c];
        }
        hs[t] = s / fmaxf(cn, 1.f);
    }
    __syncthreads();

    for (int L = 0; L < 3; L++) {
        const float* Wt = g_Wt[L];
        float a[8] = {0.f, 0.f, 0.f, 0.f, 0.f, 0.f, 0.f, 0.f};
#pragma unroll 8
        for (int k = 0; k < 64; k++) {
#pragma unroll
            for (int s = 0; s < 8; s++) {
                int kk = s * 64 + k;
                a[s] = fmaf(hs[kk], Wt[(size_t)kk * INF + t], a[s]);
            }
        }
        const float* bb = (L == 0) ? b0 : ((L == 1) ? b1 : bf);
        float v = ((a[0] + a[1]) + (a[2] + a[3])) + ((a[4] + a[5]) + (a[6] + a[7])) + bb[t];
        if (L < 2) {
            v = v * (1.f / (1.f + __expf(-v)));
            __syncthreads();
            hs[t] = v;
            __syncthreads();
        } else {
            g_hfinal[(size_t)c * INF + t] = v;
        }
    }
}

// ============================================================================
// Kernel 5: scatter out[p][:] = h_final[cid[p]][:] (R8: 42.7us @ 62% DRAM).
// ============================================================================
__global__ void scatter_kernel(float* __restrict__ out) {
    __shared__ int sc[64];
    const int t = threadIdx.x;                 // 0..255
    const int p0 = blockIdx.x * 64;
    if (t < 64) sc[t] = g_cid[p0 + t];
    __syncthreads();
    const int pl = t >> 7;                     // 0 or 1
    const int f4 = t & 127;                    // float4 index within 512-float row
    const float4* h4 = (const float4*)g_hfinal;
    float4* o4 = (float4*)out;
#pragma unroll 8
    for (int i = pl; i < 64; i += 2) {
        int c = sc[i];
        float4 v = h4[c * 128 + f4];
        __stcs(&o4[(size_t)(p0 + i) * 128 + f4], v);
    }
}

// ============================================================================
extern "C" void kernel_launch(void* const* d_in, const int* in_sizes, int n_in,
                              void* d_out, int out_size) {
    const float* x  = (const float*)d_in[0];
    const float* V0 = (const float*)d_in[1];
    const float* g0 = (const float*)d_in[2];
    const float* b0 = (const float*)d_in[3];
    const float* V1 = (const float*)d_in[4];
    const float* g1 = (const float*)d_in[5];
    const float* b1 = (const float*)d_in[6];
    const float* Wf = (const float*)d_in[7];
    const float* bf = (const float*)d_in[8];
    float* out = (float*)d_out;

    // 5 launches; slot #4 (ncu-captured) = mlp_kernel (never profiled yet).
    combo_kernel<<<640, 256>>>(x, V0, g0, V1, g1);                  // 1
    prep_wide<<<dim3(16, 16, 3), dim3(32, 8)>>>(V0, V1, Wf);        // 2
    gather_kernel<<<dim3(NC, NR), 512>>>(x);                        // 3
    mlp_kernel<<<NC, 512>>>(b0, b1, bf);                            // 4  <-- profile me
    scatter_kernel<<<2048, 256>>>(out);                             // 5
}

// round 16
// speedup vs baseline: 1.9637x; 1.1793x over previous
#include <cuda_runtime.h>

#define NPOINTS 131072
#define INF 512
#define NC 64
#define ROWSTRIDE 513   // 512 features + 1 case id per row of x
#define NR 8            // point ranges for the gather-reduce
#define RANGE 16384     // NPOINTS / NR
#define SEG 4096        // compaction segment (R12-measured best; 8192 regressed)

// -------- device scratch (static: no allocations allowed) --------
__device__ int   g_cid[NPOINTS];               // compact case ids
__device__ float g_part2[NR][NC][INF];         // per-range per-case sums (1 MB)
__device__ float g_pcnt2[NR][NC];              // per-range case counts
__device__ __align__(16) float g_hfinal[NC * INF];   // final MLP output table
__device__ float g_scale[2 * INF];             // weight-norm scales, layers 0,1
__device__ float g_Wt[3][INF * INF];           // scaled transposed weights (k-major)

// ============================================================================
// Kernel 1: fused cid-extract + weight-norm scales (disjoint block ranges).
// ============================================================================
__global__ void combo_kernel(const float* __restrict__ x,
                             const float* __restrict__ V0, const float* __restrict__ g0,
                             const float* __restrict__ V1, const float* __restrict__ g1) {
    const int b = blockIdx.x;
    const int t = threadIdx.x;
    if (b < 512) {
        const int p = b * 256 + t;
        g_cid[p] = __float2int_rn(__ldcs(x + (size_t)p * ROWSTRIDE + INF));
    } else {
        const int w    = (b - 512) * 8 + (t >> 5);   // 0..1023
        const int lane = t & 31;
        const int layer = w >> 9;
        const int o     = w & 511;
        const float* V = layer ? V1 : V0;
        const float* g = layer ? g1 : g0;
        float ss = 0.f;
        for (int k = lane; k < INF; k += 32) {
            float v = V[(size_t)o * INF + k];
            ss = fmaf(v, v, ss);
        }
        for (int off = 16; off; off >>= 1) ss += __shfl_down_sync(0xffffffffu, ss, off);
        if (lane == 0) g_scale[layer * INF + o] = g[o] * rsqrtf(ss);
    }
}

// ============================================================================
// Kernel 2: wide scaled transpose. Wt[k][o] = src[o][k] * scale[o].
// ============================================================================
__global__ void prep_wide(const float* __restrict__ V0, const float* __restrict__ V1,
                          const float* __restrict__ Wf) {
    __shared__ float tile[32][33];
    const int m = blockIdx.z;                        // 0: V0, 1: V1, 2: Wf
    const float* src = (m == 0) ? V0 : ((m == 1) ? V1 : Wf);
    const int ob = blockIdx.y * 32;
    const int kb = blockIdx.x * 32;
    const int tx = threadIdx.x, ty = threadIdx.y;
#pragma unroll
    for (int j = 0; j < 32; j += 8) {
        int o = ob + ty + j;
        float sc = (m < 2) ? g_scale[m * INF + o] : 1.f;
        tile[ty + j][tx] = src[(size_t)o * INF + kb + tx] * sc;
    }
    __syncthreads();
#pragma unroll
    for (int j = 0; j < 32; j += 8) {
        g_Wt[m][(size_t)(kb + ty + j) * INF + ob + tx] = tile[tx][ty + j];
    }
}

// ============================================================================
// Kernel 3: gather-reduce (R12: 58.1us @ 59.5% DRAM with SEG=4096).
// ============================================================================
__global__ __launch_bounds__(512, 2)
void gather_kernel(const float* __restrict__ x) {
    __shared__ int smatch[SEG];
    __shared__ int scount;
    const int c = blockIdx.x;                  // case 0..63
    const int r = blockIdx.y;                  // range 0..7
    const int t = threadIdx.x;                 // feature 0..511
    const int base = r * RANGE;

    float acc0 = 0.f, acc1 = 0.f;
    int total = 0;

    for (int seg = 0; seg < RANGE / SEG; seg++) {
        if (t == 0) scount = 0;
        __syncthreads();
        const int sbase = base + seg * SEG;
        for (int i = t; i < SEG; i += 512) {
            if (g_cid[sbase + i] == c)
                smatch[atomicAdd(&scount, 1)] = sbase + i;
        }
        __syncthreads();
        const int n = scount;
        total += n;
        for (int j = 0; j < n; j += 8) {
            float v[8];
#pragma unroll
            for (int i = 0; i < 8; i++) {
                v[i] = 0.f;
                if (j + i < n) {
                    int p = smatch[j + i];
                    v[i] = __ldcs(x + (size_t)p * ROWSTRIDE + t);
                }
            }
            acc0 += ((v[0] + v[1]) + (v[2] + v[3]));
            acc1 += ((v[4] + v[5]) + (v[6] + v[7]));
        }
        __syncthreads();                       // protect smatch/scount reuse
    }
    g_part2[r][c][t] = acc0 + acc1;
    if (t == 0) g_pcnt2[r][c] = (float)total;
}

// ============================================================================
// Kernel 4: fused mean-merge + 3-layer MLP, one case per block, 1024 threads:
// thread (o = t&511, ks = t>>9) accumulates k-half [ks*256, ks*256+256) with
// 8 independent accumulators (8 outstanding L2 loads); halves combined via
// smem sred. R14 profile showed 512-thread version latency-starved (102us,
// issue 7.5%): halving loads/thread + doubling warps attacks exactly that.
// ============================================================================
__global__ __launch_bounds__(1024)
void mlp_kernel(const float* __restrict__ b0, const float* __restrict__ b1,
                const float* __restrict__ bf) {
    __shared__ float hs[INF];
    __shared__ float sred[INF];
    const int t  = threadIdx.x;
    const int o  = t & 511;
    const int ks = t >> 9;                     // 0 or 1
    const int c  = blockIdx.x;
    const int kbase = ks * 256;

    if (ks == 0) {
        float s = 0.f, cn = 0.f;
#pragma unroll
        for (int r = 0; r < NR; r++) {
            s  += g_part2[r][c][o];
            cn += g_pcnt2[r][c];
        }
        hs[o] = s / fmaxf(cn, 1.f);
    }
    __syncthreads();

    for (int L = 0; L < 3; L++) {
        const float* Wt = g_Wt[L];
        float a[8] = {0.f, 0.f, 0.f, 0.f, 0.f, 0.f, 0.f, 0.f};
#pragma unroll 4
        for (int k = 0; k < 32; k++) {
#pragma unroll
            for (int s = 0; s < 8; s++) {
                int kk = kbase + s * 32 + k;
                a[s] = fmaf(hs[kk], Wt[(size_t)kk * INF + o], a[s]);
            }
        }
        float part = ((a[0] + a[1]) + (a[2] + a[3])) + ((a[4] + a[5]) + (a[6] + a[7]));
        __syncthreads();                       // protect sred reuse across layers
        if (ks == 1) sred[o] = part;
        __syncthreads();
        if (ks == 0) {
            const float* bb = (L == 0) ? b0 : ((L == 1) ? b1 : bf);
            float v = part + sred[o] + bb[o];
            if (L < 2) {
                v = v * (1.f / (1.f + __expf(-v)));
                hs[o] = v;
            } else {
                g_hfinal[(size_t)c * INF + o] = v;
            }
        }
        __syncthreads();                       // hs ready for next layer
    }
}

// ============================================================================
// Kernel 5: scatter out[p][:] = h_final[cid[p]][:] (R8: 42.7us @ 62% DRAM).
// ============================================================================
__global__ void scatter_kernel(float* __restrict__ out) {
    __shared__ int sc[64];
    const int t = threadIdx.x;                 // 0..255
    const int p0 = blockIdx.x * 64;
    if (t < 64) sc[t] = g_cid[p0 + t];
    __syncthreads();
    const int pl = t >> 7;                     // 0 or 1
    const int f4 = t & 127;                    // float4 index within 512-float row
    const float4* h4 = (const float4*)g_hfinal;
    float4* o4 = (float4*)out;
#pragma unroll 8
    for (int i = pl; i < 64; i += 2) {
        int c = sc[i];
        float4 v = h4[c * 128 + f4];
        __stcs(&o4[(size_t)(p0 + i) * 128 + f4], v);
    }
}

// ============================================================================
extern "C" void kernel_launch(void* const* d_in, const int* in_sizes, int n_in,
                              void* d_out, int out_size) {
    const float* x  = (const float*)d_in[0];
    const float* V0 = (const float*)d_in[1];
    const float* g0 = (const float*)d_in[2];
    const float* b0 = (const float*)d_in[3];
    const float* V1 = (const float*)d_in[4];
    const float* g1 = (const float*)d_in[5];
    const float* b1 = (const float*)d_in[6];
    const float* Wf = (const float*)d_in[7];
    const float* bf = (const float*)d_in[8];
    float* out = (float*)d_out;

    // 5 launches; slot #4 (ncu-captured) = mlp_kernel (verify the fix).
    combo_kernel<<<640, 256>>>(x, V0, g0, V1, g1);                  // 1
    prep_wide<<<dim3(16, 16, 3), dim3(32, 8)>>>(V0, V1, Wf);        // 2
    gather_kernel<<<dim3(NC, NR), 512>>>(x);                        // 3
    mlp_kernel<<<NC, 1024>>>(b0, b1, bf);                           // 4  <-- profile me
    scatter_kernel<<<2048, 256>>>(out);                             // 5
}